// round 14
// baseline (speedup 1.0000x reference)
#include <cuda_runtime.h>
#include <cuda_fp16.h>
#include <cuda_fp8.h>
#include <cstdint>

#define LOG2E_F 1.4426950408889634f
#define LN2_F   0.6931471805599453f

constexpr int NB = 64;       // batch N
constexpr int TT = 256;      // T
constexpr int VV = 32000;    // vocab
constexpr int EE = 256;      // embed dim
constexpr int KC = 128;      // clusters K
constexpr int RR = (TT - 1) * NB;   // 16320 (t,n) rows
constexpr int RPAD = 16384;         // padded unique-slot capacity
constexpr int VTILES = VV / 64;     // 500

// ------- static scratch (__device__ globals; no allocation allowed) -------
__device__ __align__(16) __nv_fp8_storage_t d_P8[(size_t)RPAD * KC * KC]; // [slot][i][j] fp8 probs
__device__ __align__(16) float  d_LogitsT[(size_t)VV * KC];  // [v][c]
__device__ __align__(16) __half d_Ah[(size_t)RPAD * EE]; // unique-token embeds f16
__device__ __align__(16) __half d_Bh[(size_t)KC * KC * EE]; // trans_w f16
__device__ float  d_PM[VTILES * KC];
__device__ float  d_PS[VTILES * KC];
__device__ float  d_RowLse[KC];
__device__ float  d_Chain[NB];
__device__ int    d_Mark[VV];
__device__ int    d_Slot[VV];
__device__ int    d_Inv[RPAD];
__device__ int    d_RowSlot[RR];
__device__ int    d_Uc;

__device__ __forceinline__ uint32_t smem_u32(const void* p) {
    uint32_t a;
    asm("{ .reg .u64 t; cvta.to.shared.u64 t, %1; cvt.u32.u64 %0, t; }" : "=r"(a) : "l"(p));
    return a;
}
__device__ __forceinline__ void cpa16(uint32_t saddr, const void* g) {
    asm volatile("cp.async.cg.shared.global [%0], [%1], 16;" :: "r"(saddr), "l"(g));
}
__device__ __forceinline__ void cpa4(uint32_t saddr, const void* g) {
    asm volatile("cp.async.ca.shared.global [%0], [%1], 4;" :: "r"(saddr), "l"(g));
}
__device__ __forceinline__ void ldsm_x4(uint32_t& r0, uint32_t& r1, uint32_t& r2, uint32_t& r3,
                                        uint32_t addr) {
    asm volatile("ldmatrix.sync.aligned.m8n8.x4.shared.b16 {%0,%1,%2,%3}, [%4];"
                 : "=r"(r0), "=r"(r1), "=r"(r2), "=r"(r3) : "r"(addr));
}
// f16 inputs, f16 accumulators (2 regs C/D)
__device__ __forceinline__ void mma_f16acc(uint32_t& d0, uint32_t& d1,
                                           uint32_t a0, uint32_t a1, uint32_t a2, uint32_t a3,
                                           uint32_t b0, uint32_t b1) {
    asm volatile("mma.sync.aligned.m16n8k16.row.col.f16.f16.f16.f16 "
                 "{%0,%1}, {%2,%3,%4,%5}, {%6,%7}, {%0,%1};"
                 : "+r"(d0), "+r"(d1)
                 : "r"(a0), "r"(a1), "r"(a2), "r"(a3), "r"(b0), "r"(b1));
}

__device__ __forceinline__ float warpMax(float v) {
#pragma unroll
    for (int o = 16; o; o >>= 1) v = fmaxf(v, __shfl_xor_sync(0xffffffffu, v, o));
    return v;
}
__device__ __forceinline__ float warpSum(float v) {
#pragma unroll
    for (int o = 16; o; o >>= 1) v += __shfl_xor_sync(0xffffffffu, v, o);
    return v;
}

// =====================================================================
// Token dedup
// =====================================================================
__global__ void __launch_bounds__(256) k_zero()
{
    int i = blockIdx.x * 256 + threadIdx.x;
    if (i < VV) d_Mark[i] = 0;
}

__global__ void __launch_bounds__(256) k_mark(const int* __restrict__ x)
{
    int r = blockIdx.x * 256 + threadIdx.x;
    if (r < RR) {
        int t = r >> 6, n = r & 63;
        d_Mark[x[n * TT + t]] = 1;
    }
}

__global__ void __launch_bounds__(1024) k_slot()
{
    __shared__ int wsum[32];
    __shared__ int sbase;
    const int tid = threadIdx.x, lane = tid & 31, wid = tid >> 5;
    if (tid == 0) sbase = 0;
    __syncthreads();

    for (int c = 0; c < 32; c++) {
        int v = c * 1024 + tid;
        int mv = (v < VV) ? d_Mark[v] : 0;
        int sc = mv;
#pragma unroll
        for (int o = 1; o < 32; o <<= 1) {
            int t2 = __shfl_up_sync(0xffffffffu, sc, o);
            if (lane >= o) sc += t2;
        }
        if (lane == 31) wsum[wid] = sc;
        __syncthreads();
        if (wid == 0) {
            int wv = wsum[lane];
#pragma unroll
            for (int o = 1; o < 32; o <<= 1) {
                int t2 = __shfl_up_sync(0xffffffffu, wv, o);
                if (lane >= o) wv += t2;
            }
            wsum[lane] = wv;
        }
        __syncthreads();
        int excl = sc - mv + (wid ? wsum[wid - 1] : 0);
        if (mv) {
            int slot = sbase + excl;
            d_Slot[v] = slot;
            d_Inv[slot] = v;
        }
        __syncthreads();
        if (tid == 0) sbase += wsum[31];
        __syncthreads();
    }
    if (tid == 0) d_Uc = sbase;
}

__global__ void __launch_bounds__(256) k_rowslot(const int* __restrict__ x)
{
    int r = blockIdx.x * 256 + threadIdx.x;
    if (r < RR) {
        int t = r >> 6, n = r & 63;
        d_RowSlot[r] = d_Slot[x[n * TT + t]];
    }
}

// =====================================================================
// Operand prep -> f16 (unique tokens only)
// =====================================================================
__global__ void __launch_bounds__(64) k_prepA(const float* __restrict__ embed_w)
{
    const int u = blockIdx.x;
    if (u >= d_Uc) return;
    const int tid = threadIdx.x;
    int tok = d_Inv[u];
    float4 f = *reinterpret_cast<const float4*>(embed_w + (size_t)tok * EE + tid * 4);
    union { __half2 h[2]; uint2 q; } pk;
    pk.h[0] = __floats2half2_rn(f.x, f.y);
    pk.h[1] = __floats2half2_rn(f.z, f.w);
    *reinterpret_cast<uint2*>(d_Ah + (size_t)u * EE + tid * 4) = pk.q;
}

__global__ void __launch_bounds__(256) k_prepB(const float* __restrict__ trans_w)
{
    size_t idx = (size_t)blockIdx.x * blockDim.x + threadIdx.x;
    float4 f = *reinterpret_cast<const float4*>(trans_w + idx * 4);
    union { __half2 h[2]; uint2 q; } pk;
    pk.h[0] = __floats2half2_rn(f.x, f.y);
    pk.h[1] = __floats2half2_rn(f.z, f.w);
    *reinterpret_cast<uint2*>(d_Bh + idx * 4) = pk.q;
}

// =====================================================================
// Phase A v3: B-stationary, continuous cross-Mt cp.async pipeline.
// CTA = (Mt-group of 8, iC). B (128x256 f16) in smem once; A stages
// cycle through a global k-counter so the pipeline never drains between
// Mt tiles; epilogue runs in a dedicated buffer concurrent with the
// next tile's loads. 256 threads, 2 CTAs/SM.
// =====================================================================
constexpr int NKT      = EE / 32;       // 8
constexpr int MT_GROUP = 8;
constexpr int AROWB    = 80;            // A stage row stride
constexpr int ASTAGE   = 128 * AROWB;   // 10240
constexpr int BROWB    = 528;           // 512B data + 16 pad
constexpr int BBYTES   = 128 * BROWB;   // 67584
constexpr int EPOFF    = BBYTES + 3 * ASTAGE;   // 98304
constexpr int ESTRIDE  = 66;            // epilogue u32 row stride (64 rows)
constexpr int EPBYTES  = 64 * ESTRIDE * 4;      // 16896
constexpr int SMEM_MMA = EPOFF + EPBYTES;       // 115200

__device__ __forceinline__ void load_Astage(uint32_t Asm, int kk, int Mt0, int tid)
{
    const int Mt = Mt0 + (kk >> 3);
    const int kt = kk & 7;
    const uint32_t abase = Asm + (kk % 3) * ASTAGE;
#pragma unroll
    for (int it = 0; it < 2; it++) {
        int chunk = tid + it * 256;        // 0..511
        int row   = chunk >> 2;
        int c     = chunk & 3;
        const __half* g = d_Ah + ((size_t)(Mt * 128 + row)) * EE + kt * 32 + c * 8;
        cpa16(abase + row * AROWB + c * 16, g);
    }
}

__global__ void __launch_bounds__(256, 2) k_mma(int dummy)
{
    const int U = d_Uc;
    extern __shared__ char smem[];
    const uint32_t Bsm = smem_u32(smem);
    const uint32_t Asm = Bsm + BBYTES;
    const int iC  = blockIdx.y;
    const int tid = threadIdx.x;
    const int wid = tid >> 5;
    const int lane = tid & 31;
    const int wm = (wid & 1) * 64;
    const int wn = (wid >> 1) * 32;
    const int lr = lane & 15;
    const int lu = lane >> 4;

    const int Mt0 = blockIdx.x * MT_GROUP;
    int remain = (U - Mt0 * 128 + 127) >> 7;   // tiles remaining from Mt0
    if (remain <= 0) return;
    const int gcnt = remain < MT_GROUP ? remain : MT_GROUP;
    const int KTOT = gcnt * NKT;

    // ---- load full B tile (iC) once ----
    {
        const __half* gB = d_Bh + (size_t)iC * 128 * EE;
#pragma unroll
        for (int it = 0; it < 16; it++) {
            int chunk = tid + it * 256;    // 0..4095
            int row   = chunk >> 5;
            int c     = chunk & 31;
            cpa16(Bsm + row * BROWB + c * 16, gB + (size_t)row * EE + c * 8);
        }
        asm volatile("cp.async.commit_group;" ::: "memory");
    }

    // A prologue
    load_Astage(Asm, 0, Mt0, tid);
    asm volatile("cp.async.commit_group;" ::: "memory");
    load_Astage(Asm, 1, Mt0, tid);
    asm volatile("cp.async.commit_group;" ::: "memory");

    uint32_t acc[4][4][2];
#pragma unroll
    for (int a = 0; a < 4; a++)
#pragma unroll
        for (int b = 0; b < 4; b++) { acc[a][b][0] = 0u; acc[a][b][1] = 0u; }

    uint32_t* ep = reinterpret_cast<uint32_t*>(smem + EPOFF);  // [64][ESTRIDE]
    const int er = lane >> 2;
    const int uc = lane & 3;

    for (int kk = 0; kk < KTOT; kk++) {
        const int kt = kk & 7;
        asm volatile("cp.async.wait_group %0;" :: "n"(1) : "memory");
        __syncthreads();
        if (kk + 2 < KTOT) load_Astage(Asm, kk + 2, Mt0, tid);
        asm volatile("cp.async.commit_group;" ::: "memory");

        const uint32_t Abase = Asm + (kk % 3) * ASTAGE;
#pragma unroll
        for (int s = 0; s < 2; s++) {
            uint32_t af[4][4];
#pragma unroll
            for (int mi = 0; mi < 4; mi++)
                ldsm_x4(af[mi][0], af[mi][1], af[mi][2], af[mi][3],
                        Abase + (wm + mi * 16 + lr) * AROWB + (2 * s + lu) * 16);
            uint32_t bf[2][4];
#pragma unroll
            for (int p = 0; p < 2; p++)
                ldsm_x4(bf[p][0], bf[p][1], bf[p][2], bf[p][3],
                        Bsm + (wn + p * 16 + lr) * BROWB + kt * 64 + (2 * s + lu) * 16);
#pragma unroll
            for (int mi = 0; mi < 4; mi++)
#pragma unroll
                for (int ni = 0; ni < 4; ni++) {
                    int p = ni >> 1, hi = ni & 1;
                    mma_f16acc(acc[mi][ni][0], acc[mi][ni][1],
                               af[mi][0], af[mi][1], af[mi][2], af[mi][3],
                               bf[p][hi], bf[p][2 + hi]);
                }
        }

        if (kt == 7) {
            // epilogue for tile Mt (dedicated buffer; next-Mt loads in flight)
            const int Mt = Mt0 + (kk >> 3);
            __syncthreads();
#pragma unroll
            for (int h = 0; h < 2; h++) {
                if ((wid & 1) == h) {
#pragma unroll
                    for (int mi = 0; mi < 4; mi++)
#pragma unroll
                        for (int ni = 0; ni < 4; ni++) {
                            int lrow = mi * 16 + er;
                            int ucol = (wn >> 1) + ni * 4 + uc;
                            ep[(size_t)lrow * ESTRIDE + ucol] = acc[mi][ni][0];
                            ep[(size_t)(lrow + 8) * ESTRIDE + ucol] = acc[mi][ni][1];
                        }
                }
                __syncthreads();
                {
                    const int lrow = tid >> 2;
                    const int qtr  = tid & 3;
                    const int r    = Mt * 128 + h * 64 + lrow;
                    float v[32];
                    const uint32_t* rp = ep + (size_t)lrow * ESTRIDE + qtr * 16;
#pragma unroll
                    for (int q = 0; q < 8; q++) {
                        uint2 u2 = *reinterpret_cast<const uint2*>(rp + q * 2);
                        float2 f0 = __half22float2(*reinterpret_cast<__half2*>(&u2.x));
                        float2 f1 = __half22float2(*reinterpret_cast<__half2*>(&u2.y));
                        v[q * 4 + 0] = f0.x; v[q * 4 + 1] = f0.y;
                        v[q * 4 + 2] = f1.x; v[q * 4 + 3] = f1.y;
                    }
                    float m = -3.4e38f;
#pragma unroll
                    for (int q = 0; q < 32; q++) m = fmaxf(m, v[q]);
                    m = fmaxf(m, __shfl_xor_sync(0xffffffffu, m, 1));
                    m = fmaxf(m, __shfl_xor_sync(0xffffffffu, m, 2));
                    float s = 0.0f;
#pragma unroll
                    for (int q = 0; q < 32; q++) { v[q] = exp2f((v[q] - m) * LOG2E_F); s += v[q]; }
                    s += __shfl_xor_sync(0xffffffffu, s, 1);
                    s += __shfl_xor_sync(0xffffffffu, s, 2);
                    float inv = 1.0f / s;
                    if (r < U) {
                        union { __nv_fp8x2_storage_t hh[16]; uint4 q4[2]; } pk;
#pragma unroll
                        for (int q = 0; q < 16; q++)
                            pk.hh[q] = __nv_cvt_float2_to_fp8x2(
                                make_float2(v[2 * q] * inv, v[2 * q + 1] * inv),
                                __NV_SATFINITE, __NV_E4M3);
                        uint4* op = reinterpret_cast<uint4*>(
                            d_P8 + ((size_t)r * KC + iC) * KC + qtr * 32);
                        op[0] = pk.q4[0];
                        op[1] = pk.q4[1];
                    }
                }
                __syncthreads();
            }
            // reset accumulators for next tile
#pragma unroll
            for (int a = 0; a < 4; a++)
#pragma unroll
                for (int b = 0; b < 4; b++) { acc[a][b][0] = 0u; acc[a][b][1] = 0u; }
        }
    }
    (void)dummy;
}

// =====================================================================
// Emission logits GEMM + partial lse + parallel final lse
// =====================================================================
__global__ void __launch_bounds__(256) k_emit_gemm(const float* __restrict__ emit_w,
                                                   const float* __restrict__ emb_cluster_w)
{
    const int vt = blockIdx.x;
    __shared__ float avs[16][65];
    __shared__ float bvs[16][129];
    __shared__ float pmS[8][128];
    __shared__ float psS[8][128];

    const int tid   = threadIdx.x;
    const int lane  = tid & 31;
    const int wg    = tid >> 5;
    const int rbase = wg * 8;
    const int cbase = lane * 4;

    float acc[8][4];
#pragma unroll
    for (int a = 0; a < 8; a++)
#pragma unroll
        for (int b = 0; b < 4; b++) acc[a][b] = 0.0f;

    for (int k0 = 0; k0 < KC; k0 += 16) {
#pragma unroll
        for (int it = 0; it < 4; it++) {
            int u = tid + it * 256;
            int kk = u & 15, row = u >> 4;
            avs[kk][row] = emit_w[(size_t)(vt * 64 + row) * KC + k0 + kk];
        }
#pragma unroll
        for (int it = 0; it < 8; it++) {
            int u = tid + it * 256;
            int kk = u & 15, c = u >> 4;
            bvs[kk][c] = emb_cluster_w[(size_t)c * KC + k0 + kk];
        }
        __syncthreads();
#pragma unroll
        for (int kk = 0; kk < 16; kk++) {
            float av[8], bv[4];
#pragma unroll
            for (int r2 = 0; r2 < 8; r2++) av[r2] = avs[kk][rbase + r2];
#pragma unroll
            for (int c2 = 0; c2 < 4; c2++) bv[c2] = bvs[kk][cbase + c2];
#pragma unroll
            for (int r2 = 0; r2 < 8; r2++)
#pragma unroll
                for (int c2 = 0; c2 < 4; c2++)
                    acc[r2][c2] = fmaf(av[r2], bv[c2], acc[r2][c2]);
        }
        __syncthreads();
    }

    float pm[4], ps[4];
#pragma unroll
    for (int c2 = 0; c2 < 4; c2++) { pm[c2] = -3.4e38f; ps[c2] = 0.0f; }
#pragma unroll
    for (int r2 = 0; r2 < 8; r2++) {
        int v = vt * 64 + rbase + r2;
        float4 f4 = make_float4(acc[r2][0], acc[r2][1], acc[r2][2], acc[r2][3]);
        *reinterpret_cast<float4*>(&d_LogitsT[(size_t)v * KC + cbase]) = f4;
#pragma unroll
        for (int c2 = 0; c2 < 4; c2++) pm[c2] = fmaxf(pm[c2], acc[r2][c2]);
    }
#pragma unroll
    for (int r2 = 0; r2 < 8; r2++)
#pragma unroll
        for (int c2 = 0; c2 < 4; c2++)
            ps[c2] += exp2f((acc[r2][c2] - pm[c2]) * LOG2E_F);

#pragma unroll
    for (int c2 = 0; c2 < 4; c2++) { pmS[wg][cbase + c2] = pm[c2]; psS[wg][cbase + c2] = ps[c2]; }
    __syncthreads();
    if (tid < 128) {
        float m = pmS[0][tid];
#pragma unroll
        for (int w = 1; w < 8; w++) m = fmaxf(m, pmS[w][tid]);
        float s = 0.0f;
#pragma unroll
        for (int w = 0; w < 8; w++) s += psS[w][tid] * exp2f((pmS[w][tid] - m) * LOG2E_F);
        d_PM[vt * KC + tid] = m;
        d_PS[vt * KC + tid] = s;
    }
}

__global__ void __launch_bounds__(256) k_lse_final()
{
    __shared__ float sred[256];
    const int c   = blockIdx.x;
    const int tid = threadIdx.x;

    float m = -3.4e38f;
    for (int b = tid; b < VTILES; b += 256) m = fmaxf(m, d_PM[b * KC + c]);
    sred[tid] = m;
    __syncthreads();
    for (int o = 128; o; o >>= 1) {
        if (tid < o) sred[tid] = fmaxf(sred[tid], sred[tid + o]);
        __syncthreads();
    }
    float gm = sred[0];
    __syncthreads();

    float s = 0.0f;
    for (int b = tid; b < VTILES; b += 256)
        s += d_PS[b * KC + c] * exp2f((d_PM[b * KC + c] - gm) * LOG2E_F);
    sred[tid] = s;
    __syncthreads();
    for (int o = 128; o; o >>= 1) {
        if (tid < o) sred[tid] += sred[tid + o];
        __syncthreads();
    }
    if (tid == 0) d_RowLse[c] = gm + log2f(sred[0]) * LN2_F;
}

// =====================================================================
// Phase B: sequential scan, 256 threads/chain, 3-stage cp.async pipeline
// =====================================================================
constexpr int PBUF8     = KC * KC;               // 16384 bytes/stage
constexpr int EABUF     = KC * 4;                // 512
constexpr int SCAN_SMEM = 3 * (PBUF8 + EABUF);   // 50688

__global__ void __launch_bounds__(256) k_scan(const int* __restrict__ x,
                                              const float* __restrict__ start_w,
                                              const float* __restrict__ start_b)
{
    extern __shared__ __align__(16) char ps[];
    __shared__ float w_s[2][128];
    __shared__ float red[2][8][132];
    __shared__ float smax[2][8];
    __shared__ float ssum[8];

    const int n    = blockIdx.x;
    const int tid  = threadIdx.x;
    const int lane = tid & 31;
    const int wid  = tid >> 5;       // 0..7
    const int j    = tid & 127;      // duplicated across halves
    const int jg   = lane;
    const int ic   = wid;            // i-chunk of 16
    const uint32_t sbase  = smem_u32(ps);
    const uint32_t eabase = sbase + 3 * PBUF8;
    const float rl = d_RowLse[j];

    auto prefetch = [&](int t) {
        const int r = t * NB + n;
        const int slot = d_RowSlot[r];
        const char* gp = reinterpret_cast<const char*>(d_P8 + (size_t)slot * KC * KC);
        uint32_t dst = sbase + (t % 3) * PBUF8;
#pragma unroll
        for (int k = 0; k < 4; k++) {
            int idx = tid + k * 256;
            cpa16(dst + idx * 16, gp + idx * 16);
        }
        if (tid < 128) {
            const int w = x[n * TT + t + 1];
            cpa4(eabase + (t % 3) * EABUF + tid * 4, d_LogitsT + (size_t)w * KC + tid);
        }
    };

    prefetch(0);
    asm volatile("cp.async.commit_group;" ::: "memory");
    prefetch(1);
    asm volatile("cp.async.commit_group;" ::: "memory");

    float a0 = start_w[j] + start_b[j];
    float m = warpMax(a0);
    if (lane == 0) smax[0][wid] = m;
    __syncthreads();
    m = smax[0][0];
#pragma unroll
    for (int w = 1; w < 8; w++) m = fmaxf(m, smax[0][w]);
    float e = exp2f((a0 - m) * LOG2E_F);
    float s = warpSum(e);
    if (lane == 0) ssum[wid] = s;
    __syncthreads();
    s = ssum[0] + ssum[1] + ssum[2] + ssum[3];   // warps 0-3 cover all j once
    float alpha = a0 - m - log2f(s) * LN2_F;
    __syncthreads();

    for (int t = 0; t < TT - 1; t++) {
        const int p = t & 1;
        if (t + 2 < TT - 1) prefetch(t + 2);
        asm volatile("cp.async.commit_group;" ::: "memory");

        float mm = warpMax(alpha);
        if (lane == 0) smax[p][wid] = mm;
        __syncthreads();
        mm = smax[p][0];
#pragma unroll
        for (int w = 1; w < 8; w++) mm = fmaxf(mm, smax[p][w]);
        if (tid < 128) w_s[p][j] = exp2f((alpha - mm) * LOG2E_F);
        asm volatile("cp.async.wait_group %0;" :: "n"(2) : "memory");
        __syncthreads();

        const size_t off = (size_t)(t % 3) * PBUF8;
        float acc0 = 0.f, acc1 = 0.f, acc2 = 0.f, acc3 = 0.f;
#pragma unroll
        for (int ii = 0; ii < 16; ii++) {
            const int i = ic * 16 + ii;
            uint32_t u = *reinterpret_cast<const uint32_t*>(ps + off + i * 128 + jg * 4);
            float wi = w_s[p][i];
            __half2_raw r01 = __nv_cvt_fp8x2_to_halfraw2(
                (__nv_fp8x2_storage_t)(u & 0xffffu), __NV_E4M3);
            __half2_raw r23 = __nv_cvt_fp8x2_to_halfraw2(
                (__nv_fp8x2_storage_t)(u >> 16), __NV_E4M3);
            float2 f01 = __half22float2(*reinterpret_cast<__half2*>(&r01));
            float2 f23 = __half22float2(*reinterpret_cast<__half2*>(&r23));
            acc0 = fmaf(wi, f01.x, acc0);
            acc1 = fmaf(wi, f01.y, acc1);
            acc2 = fmaf(wi, f23.x, acc2);
            acc3 = fmaf(wi, f23.y, acc3);
        }
        red[p][ic][jg * 4 + 0] = acc0;
        red[p][ic][jg * 4 + 1] = acc1;
        red[p][ic][jg * 4 + 2] = acc2;
        red[p][ic][jg * 4 + 3] = acc3;
        __syncthreads();
        float tot = red[p][0][j];
#pragma unroll
        for (int w = 1; w < 8; w++) tot += red[p][w][j];
        float ea = *reinterpret_cast<const float*>(ps + 3 * PBUF8 + (t % 3) * EABUF + j * 4);
        alpha = mm + log2f(tot) * LN2_F + (ea - rl);
    }

    float mm = warpMax(alpha);
    if (lane == 0) smax[0][wid] = mm;
    __syncthreads();
    mm = smax[0][0];
#pragma unroll
    for (int w = 1; w < 8; w++) mm = fmaxf(mm, smax[0][w]);
    float ee = exp2f((alpha - mm) * LOG2E_F);
    float ss = warpSum(ee);
    if (lane == 0) ssum[wid] = ss;
    __syncthreads();
    if (tid == 0) {
        float stot = ssum[0] + ssum[1] + ssum[2] + ssum[3];
        d_Chain[n] = mm + log2f(stot) * LN2_F;
    }
}

__global__ void k_final(float* out, int out_size)
{
    __shared__ float sh;
    if (threadIdx.x == 0) {
        float s = 0.0f;
        for (int i = 0; i < NB; i++) s += d_Chain[i];
        sh = -s / (float)NB;
    }
    __syncthreads();
    for (int i = threadIdx.x; i < out_size; i += blockDim.x) out[i] = sh;
}

extern "C" void kernel_launch(void* const* d_in, const int* in_sizes, int n_in,
                              void* d_out, int out_size)
{
    (void)in_sizes; (void)n_in;
    const int*   x             = (const int*)d_in[0];
    const float* embed_w       = (const float*)d_in[1];
    const float* trans_w       = (const float*)d_in[2];
    const float* start_w       = (const float*)d_in[3];
    const float* start_b       = (const float*)d_in[4];
    const float* emb_cluster_w = (const float*)d_in[5];
    const float* emit_w        = (const float*)d_in[6];

    cudaFuncSetAttribute(k_mma, cudaFuncAttributeMaxDynamicSharedMemorySize, SMEM_MMA);
    cudaFuncSetAttribute(k_scan, cudaFuncAttributeMaxDynamicSharedMemorySize, SCAN_SMEM);

    // host-side resources (created once; no device memory involved)
    static cudaStream_t s1 = [] { cudaStream_t s; cudaStreamCreateWithFlags(&s, cudaStreamNonBlocking); return s; }();
    static cudaStream_t s2 = [] { cudaStream_t s; cudaStreamCreateWithFlags(&s, cudaStreamNonBlocking); return s; }();
    static cudaEvent_t evF = [] { cudaEvent_t e; cudaEventCreateWithFlags(&e, cudaEventDisableTiming); return e; }();
    static cudaEvent_t evE = [] { cudaEvent_t e; cudaEventCreateWithFlags(&e, cudaEventDisableTiming); return e; }();
    static cudaEvent_t evB = [] { cudaEvent_t e; cudaEventCreateWithFlags(&e, cudaEventDisableTiming); return e; }();

    // fork side streams off the capture (legacy) stream
    cudaEventRecord(evF, 0);
    cudaStreamWaitEvent(s1, evF, 0);
    cudaStreamWaitEvent(s2, evF, 0);

    // s1: emission chain (only needed by k_scan)
    k_emit_gemm<<<VTILES, 256, 0, s1>>>(emit_w, emb_cluster_w);
    k_lse_final<<<KC, 256, 0, s1>>>();
    cudaEventRecord(evE, s1);

    // s2: trans_w conversion (only needed by k_mma)
    k_prepB<<<4096, 256, 0, s2>>>(trans_w);
    cudaEventRecord(evB, s2);

    // main: dedup chain -> prepA -> (join prepB) -> mma -> (join emit) -> scan
    k_zero<<<(VV + 255) / 256, 256>>>();
    k_mark<<<(RR + 255) / 256, 256>>>(x);
    k_slot<<<1, 1024>>>();
    k_rowslot<<<(RR + 255) / 256, 256>>>(x);
    k_prepA<<<RPAD, 64>>>(embed_w);
    cudaStreamWaitEvent(0, evB, 0);
    k_mma<<<dim3(128 / MT_GROUP, 128), 256, SMEM_MMA>>>(0);
    cudaStreamWaitEvent(0, evE, 0);
    k_scan<<<NB, 256, SCAN_SMEM>>>(x, start_w, start_b);
    k_final<<<1, 64>>>((float*)d_out, out_size);
}

// round 16
// speedup vs baseline: 1.0743x; 1.0743x over previous
#include <cuda_runtime.h>
#include <cuda_fp16.h>
#include <cuda_fp8.h>
#include <cstdint>

#define LOG2E_F 1.4426950408889634f
#define LN2_F   0.6931471805599453f

constexpr int NB = 64;       // batch N
constexpr int TT = 256;      // T
constexpr int VV = 32000;    // vocab
constexpr int EE = 256;      // embed dim
constexpr int KC = 128;      // clusters K
constexpr int RR = (TT - 1) * NB;   // 16320 (t,n) rows
constexpr int RPAD = 16384;         // padded unique-slot capacity
constexpr int VTILES = VV / 64;     // 500

// ------- static scratch (__device__ globals; no allocation allowed) -------
__device__ __align__(16) __nv_fp8_storage_t d_P8[(size_t)RPAD * KC * KC]; // [slot][i][j] fp8 probs
__device__ __align__(16) float  d_LogitsT[(size_t)VV * KC];  // [v][c]
__device__ __align__(16) __half d_Ah[(size_t)RPAD * EE]; // unique-token embeds f16
__device__ __align__(16) __half d_Bh[(size_t)KC * KC * EE]; // trans_w f16
__device__ float  d_PM[VTILES * KC];
__device__ float  d_PS[VTILES * KC];
__device__ float  d_RowLse[KC];
__device__ float  d_Chain[NB];
__device__ int    d_Mark[VV];
__device__ int    d_Slot[VV];
__device__ int    d_Inv[RPAD];
__device__ int    d_RowSlot[RR];
__device__ int    d_Uc;

__device__ __forceinline__ uint32_t smem_u32(const void* p) {
    uint32_t a;
    asm("{ .reg .u64 t; cvta.to.shared.u64 t, %1; cvt.u32.u64 %0, t; }" : "=r"(a) : "l"(p));
    return a;
}
__device__ __forceinline__ void cpa16(uint32_t saddr, const void* g) {
    asm volatile("cp.async.cg.shared.global [%0], [%1], 16;" :: "r"(saddr), "l"(g));
}
__device__ __forceinline__ void cpa4(uint32_t saddr, const void* g) {
    asm volatile("cp.async.ca.shared.global [%0], [%1], 4;" :: "r"(saddr), "l"(g));
}
__device__ __forceinline__ void ldsm_x4(uint32_t& r0, uint32_t& r1, uint32_t& r2, uint32_t& r3,
                                        uint32_t addr) {
    asm volatile("ldmatrix.sync.aligned.m8n8.x4.shared.b16 {%0,%1,%2,%3}, [%4];"
                 : "=r"(r0), "=r"(r1), "=r"(r2), "=r"(r3) : "r"(addr));
}
// f16 inputs, f16 accumulators (2 regs C/D)
__device__ __forceinline__ void mma_f16acc(uint32_t& d0, uint32_t& d1,
                                           uint32_t a0, uint32_t a1, uint32_t a2, uint32_t a3,
                                           uint32_t b0, uint32_t b1) {
    asm volatile("mma.sync.aligned.m16n8k16.row.col.f16.f16.f16.f16 "
                 "{%0,%1}, {%2,%3,%4,%5}, {%6,%7}, {%0,%1};"
                 : "+r"(d0), "+r"(d1)
                 : "r"(a0), "r"(a1), "r"(a2), "r"(a3), "r"(b0), "r"(b1));
}

__device__ __forceinline__ float warpMax(float v) {
#pragma unroll
    for (int o = 16; o; o >>= 1) v = fmaxf(v, __shfl_xor_sync(0xffffffffu, v, o));
    return v;
}
__device__ __forceinline__ float warpSum(float v) {
#pragma unroll
    for (int o = 16; o; o >>= 1) v += __shfl_xor_sync(0xffffffffu, v, o);
    return v;
}

// =====================================================================
// Token dedup (atomic slot assignment; slot order run-varying but output
// is bitwise-invariant to the slot permutation)
// =====================================================================
__global__ void __launch_bounds__(256) k_zero()
{
    int i = blockIdx.x * 256 + threadIdx.x;
    if (i < VV) d_Mark[i] = 0;
    if (i == 0) d_Uc = 0;
}

__global__ void __launch_bounds__(256) k_mark(const int* __restrict__ x)
{
    int r = blockIdx.x * 256 + threadIdx.x;
    if (r < RR) {
        int t = r >> 6, n = r & 63;
        int v = x[n * TT + t];
        if (atomicCAS(&d_Mark[v], 0, 1) == 0) {
            int s = atomicAdd(&d_Uc, 1);
            d_Slot[v] = s;
            d_Inv[s] = v;
        }
    }
}

__global__ void __launch_bounds__(256) k_rowslot(const int* __restrict__ x)
{
    int r = blockIdx.x * 256 + threadIdx.x;
    if (r < RR) {
        int t = r >> 6, n = r & 63;
        d_RowSlot[r] = d_Slot[x[n * TT + t]];
    }
}

// =====================================================================
// Operand prep -> f16 (unique tokens only)
// =====================================================================
__global__ void __launch_bounds__(64) k_prepA(const float* __restrict__ embed_w)
{
    const int u = blockIdx.x;
    if (u >= d_Uc) return;
    const int tid = threadIdx.x;
    int tok = d_Inv[u];
    float4 f = *reinterpret_cast<const float4*>(embed_w + (size_t)tok * EE + tid * 4);
    union { __half2 h[2]; uint2 q; } pk;
    pk.h[0] = __floats2half2_rn(f.x, f.y);
    pk.h[1] = __floats2half2_rn(f.z, f.w);
    *reinterpret_cast<uint2*>(d_Ah + (size_t)u * EE + tid * 4) = pk.q;
}

__global__ void __launch_bounds__(256) k_prepB(const float* __restrict__ trans_w)
{
    size_t idx = (size_t)blockIdx.x * blockDim.x + threadIdx.x;
    float4 f = *reinterpret_cast<const float4*>(trans_w + idx * 4);
    union { __half2 h[2]; uint2 q; } pk;
    pk.h[0] = __floats2half2_rn(f.x, f.y);
    pk.h[1] = __floats2half2_rn(f.z, f.w);
    *reinterpret_cast<uint2*>(d_Bh + idx * 4) = pk.q;
}

// =====================================================================
// Phase A v4: B-stationary, ktile=64, 2-stage double buffer.
// 4 wait/sync windows per Mt tile; epilogue reuses the just-consumed
// A buffer while the next tile's first load is in flight.
// 256 threads, 2 CTAs/SM.
// =====================================================================
constexpr int NKT      = 4;             // 256 / 64
constexpr int MT_GROUP = 8;
constexpr int AROWB    = 144;           // 128B data + 16 pad (ldsm conflict-free)
constexpr int ASTAGE   = 128 * AROWB;   // 18432
constexpr int BROWB    = 528;           // 512B data + 16 pad
constexpr int BBYTES   = 128 * BROWB;   // 67584
constexpr int SMEM_MMA = BBYTES + 2 * ASTAGE;  // 104448
constexpr int ESTRIDE  = 66;            // epilogue u32 row stride (fits in ASTAGE)

__device__ __forceinline__ void load_Astage(uint32_t Asm, int kk, int Mt0, int tid)
{
    const int Mt = Mt0 + (kk >> 2);
    const int kt = kk & 3;
    const uint32_t abase = Asm + (kk & 1) * ASTAGE;
#pragma unroll
    for (int it = 0; it < 4; it++) {
        int chunk = tid + it * 256;        // 0..1023
        int row   = chunk >> 3;
        int c     = chunk & 7;
        const __half* g = d_Ah + ((size_t)(Mt * 128 + row)) * EE + kt * 64 + c * 8;
        cpa16(abase + row * AROWB + c * 16, g);
    }
}

__global__ void __launch_bounds__(256, 2) k_mma(int dummy)
{
    const int U = d_Uc;
    extern __shared__ char smem[];
    const uint32_t Bsm = smem_u32(smem);
    const uint32_t Asm = Bsm + BBYTES;
    const int iC  = blockIdx.y;
    const int tid = threadIdx.x;
    const int wid = tid >> 5;
    const int lane = tid & 31;
    const int wm = (wid & 1) * 64;
    const int wn = (wid >> 1) * 32;
    const int lr = lane & 15;
    const int lu = lane >> 4;

    const int Mt0 = blockIdx.x * MT_GROUP;
    int remain = (U - Mt0 * 128 + 127) >> 7;
    if (remain <= 0) return;
    const int gcnt = remain < MT_GROUP ? remain : MT_GROUP;
    const int KTOT = gcnt * NKT;

    // ---- load full B tile (iC) once ----
    {
        const __half* gB = d_Bh + (size_t)iC * 128 * EE;
#pragma unroll
        for (int it = 0; it < 16; it++) {
            int chunk = tid + it * 256;    // 0..4095
            int row   = chunk >> 5;
            int c     = chunk & 31;
            cpa16(Bsm + row * BROWB + c * 16, gB + (size_t)row * EE + c * 8);
        }
        asm volatile("cp.async.commit_group;" ::: "memory");
    }

    // A prologue: stage 0
    load_Astage(Asm, 0, Mt0, tid);
    asm volatile("cp.async.commit_group;" ::: "memory");

    uint32_t acc[4][4][2];
#pragma unroll
    for (int a = 0; a < 4; a++)
#pragma unroll
        for (int b = 0; b < 4; b++) { acc[a][b][0] = 0u; acc[a][b][1] = 0u; }

    const int er = lane >> 2;
    const int uc = lane & 3;

    for (int kk = 0; kk < KTOT; kk++) {
        const int kt = kk & 3;
        asm volatile("cp.async.wait_group %0;" :: "n"(0) : "memory");
        __syncthreads();
        if (kk + 1 < KTOT) load_Astage(Asm, kk + 1, Mt0, tid);
        asm volatile("cp.async.commit_group;" ::: "memory");

        const uint32_t Abase = Asm + (kk & 1) * ASTAGE;
#pragma unroll
        for (int s = 0; s < 4; s++) {
            uint32_t af[4][4];
#pragma unroll
            for (int mi = 0; mi < 4; mi++)
                ldsm_x4(af[mi][0], af[mi][1], af[mi][2], af[mi][3],
                        Abase + (wm + mi * 16 + lr) * AROWB + s * 32 + lu * 16);
            uint32_t bf[2][4];
#pragma unroll
            for (int p = 0; p < 2; p++)
                ldsm_x4(bf[p][0], bf[p][1], bf[p][2], bf[p][3],
                        Bsm + (wn + p * 16 + lr) * BROWB + kt * 128 + s * 32 + lu * 16);
#pragma unroll
            for (int mi = 0; mi < 4; mi++)
#pragma unroll
                for (int ni = 0; ni < 4; ni++) {
                    int p = ni >> 1, hi = ni & 1;
                    mma_f16acc(acc[mi][ni][0], acc[mi][ni][1],
                               af[mi][0], af[mi][1], af[mi][2], af[mi][3],
                               bf[p][hi], bf[p][2 + hi]);
                }
        }

        if (kt == 3) {
            // epilogue for tile Mt; reuse the just-consumed A buffer.
            // In-flight load kk+1 targets the other buffer.
            const int Mt = Mt0 + (kk >> 2);
            uint32_t* ep = reinterpret_cast<uint32_t*>(smem + BBYTES + (kk & 1) * ASTAGE);
            __syncthreads();
#pragma unroll
            for (int h = 0; h < 2; h++) {
                if ((wid & 1) == h) {
#pragma unroll
                    for (int mi = 0; mi < 4; mi++)
#pragma unroll
                        for (int ni = 0; ni < 4; ni++) {
                            int lrow = mi * 16 + er;
                            int ucol = (wn >> 1) + ni * 4 + uc;
                            ep[(size_t)lrow * ESTRIDE + ucol] = acc[mi][ni][0];
                            ep[(size_t)(lrow + 8) * ESTRIDE + ucol] = acc[mi][ni][1];
                        }
                }
                __syncthreads();
                {
                    const int lrow = tid >> 2;
                    const int qtr  = tid & 3;
                    const int r    = Mt * 128 + h * 64 + lrow;
                    float v[32];
                    const uint32_t* rp = ep + (size_t)lrow * ESTRIDE + qtr * 16;
#pragma unroll
                    for (int q = 0; q < 8; q++) {
                        uint2 u2 = *reinterpret_cast<const uint2*>(rp + q * 2);
                        float2 f0 = __half22float2(*reinterpret_cast<__half2*>(&u2.x));
                        float2 f1 = __half22float2(*reinterpret_cast<__half2*>(&u2.y));
                        v[q * 4 + 0] = f0.x; v[q * 4 + 1] = f0.y;
                        v[q * 4 + 2] = f1.x; v[q * 4 + 3] = f1.y;
                    }
                    float m = -3.4e38f;
#pragma unroll
                    for (int q = 0; q < 32; q++) m = fmaxf(m, v[q]);
                    m = fmaxf(m, __shfl_xor_sync(0xffffffffu, m, 1));
                    m = fmaxf(m, __shfl_xor_sync(0xffffffffu, m, 2));
                    float s = 0.0f;
#pragma unroll
                    for (int q = 0; q < 32; q++) { v[q] = exp2f((v[q] - m) * LOG2E_F); s += v[q]; }
                    s += __shfl_xor_sync(0xffffffffu, s, 1);
                    s += __shfl_xor_sync(0xffffffffu, s, 2);
                    float inv = 1.0f / s;
                    if (r < U) {
                        union { __nv_fp8x2_storage_t hh[16]; uint4 q4[2]; } pk;
#pragma unroll
                        for (int q = 0; q < 16; q++)
                            pk.hh[q] = __nv_cvt_float2_to_fp8x2(
                                make_float2(v[2 * q] * inv, v[2 * q + 1] * inv),
                                __NV_SATFINITE, __NV_E4M3);
                        uint4* op = reinterpret_cast<uint4*>(
                            d_P8 + ((size_t)r * KC + iC) * KC + qtr * 32);
                        op[0] = pk.q4[0];
                        op[1] = pk.q4[1];
                    }
                }
                __syncthreads();
            }
#pragma unroll
            for (int a = 0; a < 4; a++)
#pragma unroll
                for (int b = 0; b < 4; b++) { acc[a][b][0] = 0u; acc[a][b][1] = 0u; }
        }
    }
    (void)dummy;
}

// =====================================================================
// Emission logits GEMM + partial lse + parallel final lse
// =====================================================================
__global__ void __launch_bounds__(256) k_emit_gemm(const float* __restrict__ emit_w,
                                                   const float* __restrict__ emb_cluster_w)
{
    const int vt = blockIdx.x;
    __shared__ float avs[16][65];
    __shared__ float bvs[16][129];
    __shared__ float pmS[8][128];
    __shared__ float psS[8][128];

    const int tid   = threadIdx.x;
    const int lane  = tid & 31;
    const int wg    = tid >> 5;
    const int rbase = wg * 8;
    const int cbase = lane * 4;

    float acc[8][4];
#pragma unroll
    for (int a = 0; a < 8; a++)
#pragma unroll
        for (int b = 0; b < 4; b++) acc[a][b] = 0.0f;

    for (int k0 = 0; k0 < KC; k0 += 16) {
#pragma unroll
        for (int it = 0; it < 4; it++) {
            int u = tid + it * 256;
            int kk = u & 15, row = u >> 4;
            avs[kk][row] = emit_w[(size_t)(vt * 64 + row) * KC + k0 + kk];
        }
#pragma unroll
        for (int it = 0; it < 8; it++) {
            int u = tid + it * 256;
            int kk = u & 15, c = u >> 4;
            bvs[kk][c] = emb_cluster_w[(size_t)c * KC + k0 + kk];
        }
        __syncthreads();
#pragma unroll
        for (int kk = 0; kk < 16; kk++) {
            float av[8], bv[4];
#pragma unroll
            for (int r2 = 0; r2 < 8; r2++) av[r2] = avs[kk][rbase + r2];
#pragma unroll
            for (int c2 = 0; c2 < 4; c2++) bv[c2] = bvs[kk][cbase + c2];
#pragma unroll
            for (int r2 = 0; r2 < 8; r2++)
#pragma unroll
                for (int c2 = 0; c2 < 4; c2++)
                    acc[r2][c2] = fmaf(av[r2], bv[c2], acc[r2][c2]);
        }
        __syncthreads();
    }

    float pm[4], ps[4];
#pragma unroll
    for (int c2 = 0; c2 < 4; c2++) { pm[c2] = -3.4e38f; ps[c2] = 0.0f; }
#pragma unroll
    for (int r2 = 0; r2 < 8; r2++) {
        int v = vt * 64 + rbase + r2;
        float4 f4 = make_float4(acc[r2][0], acc[r2][1], acc[r2][2], acc[r2][3]);
        *reinterpret_cast<float4*>(&d_LogitsT[(size_t)v * KC + cbase]) = f4;
#pragma unroll
        for (int c2 = 0; c2 < 4; c2++) pm[c2] = fmaxf(pm[c2], acc[r2][c2]);
    }
#pragma unroll
    for (int r2 = 0; r2 < 8; r2++)
#pragma unroll
        for (int c2 = 0; c2 < 4; c2++)
            ps[c2] += exp2f((acc[r2][c2] - pm[c2]) * LOG2E_F);

#pragma unroll
    for (int c2 = 0; c2 < 4; c2++) { pmS[wg][cbase + c2] = pm[c2]; psS[wg][cbase + c2] = ps[c2]; }
    __syncthreads();
    if (tid < 128) {
        float m = pmS[0][tid];
#pragma unroll
        for (int w = 1; w < 8; w++) m = fmaxf(m, pmS[w][tid]);
        float s = 0.0f;
#pragma unroll
        for (int w = 0; w < 8; w++) s += psS[w][tid] * exp2f((pmS[w][tid] - m) * LOG2E_F);
        d_PM[vt * KC + tid] = m;
        d_PS[vt * KC + tid] = s;
    }
}

__global__ void __launch_bounds__(256) k_lse_final()
{
    __shared__ float sred[256];
    const int c   = blockIdx.x;
    const int tid = threadIdx.x;

    float m = -3.4e38f;
    for (int b = tid; b < VTILES; b += 256) m = fmaxf(m, d_PM[b * KC + c]);
    sred[tid] = m;
    __syncthreads();
    for (int o = 128; o; o >>= 1) {
        if (tid < o) sred[tid] = fmaxf(sred[tid], sred[tid + o]);
        __syncthreads();
    }
    float gm = sred[0];
    __syncthreads();

    float s = 0.0f;
    for (int b = tid; b < VTILES; b += 256)
        s += d_PS[b * KC + c] * exp2f((d_PM[b * KC + c] - gm) * LOG2E_F);
    sred[tid] = s;
    __syncthreads();
    for (int o = 128; o; o >>= 1) {
        if (tid < o) sred[tid] += sred[tid + o];
        __syncthreads();
    }
    if (tid == 0) d_RowLse[c] = gm + log2f(sred[0]) * LN2_F;
}

// =====================================================================
// Phase B: sequential scan, 256 threads/chain, 3-stage cp.async pipeline
// =====================================================================
constexpr int PBUF8     = KC * KC;               // 16384 bytes/stage
constexpr int EABUF     = KC * 4;                // 512
constexpr int SCAN_SMEM = 3 * (PBUF8 + EABUF);   // 50688

__global__ void __launch_bounds__(256) k_scan(const int* __restrict__ x,
                                              const float* __restrict__ start_w,
                                              const float* __restrict__ start_b)
{
    extern __shared__ __align__(16) char ps[];
    __shared__ float w_s[2][128];
    __shared__ float red[2][8][132];
    __shared__ float smax[2][8];
    __shared__ float ssum[8];

    const int n    = blockIdx.x;
    const int tid  = threadIdx.x;
    const int lane = tid & 31;
    const int wid  = tid >> 5;       // 0..7
    const int j    = tid & 127;      // duplicated across halves
    const int jg   = lane;
    const int ic   = wid;            // i-chunk of 16
    const uint32_t sbase  = smem_u32(ps);
    const uint32_t eabase = sbase + 3 * PBUF8;
    const float rl = d_RowLse[j];

    auto prefetch = [&](int t) {
        const int r = t * NB + n;
        const int slot = d_RowSlot[r];
        const char* gp = reinterpret_cast<const char*>(d_P8 + (size_t)slot * KC * KC);
        uint32_t dst = sbase + (t % 3) * PBUF8;
#pragma unroll
        for (int k = 0; k < 4; k++) {
            int idx = tid + k * 256;
            cpa16(dst + idx * 16, gp + idx * 16);
        }
        if (tid < 128) {
            const int w = x[n * TT + t + 1];
            cpa4(eabase + (t % 3) * EABUF + tid * 4, d_LogitsT + (size_t)w * KC + tid);
        }
    };

    prefetch(0);
    asm volatile("cp.async.commit_group;" ::: "memory");
    prefetch(1);
    asm volatile("cp.async.commit_group;" ::: "memory");

    float a0 = start_w[j] + start_b[j];
    float m = warpMax(a0);
    if (lane == 0) smax[0][wid] = m;
    __syncthreads();
    m = smax[0][0];
#pragma unroll
    for (int w = 1; w < 8; w++) m = fmaxf(m, smax[0][w]);
    float e = exp2f((a0 - m) * LOG2E_F);
    float s = warpSum(e);
    if (lane == 0) ssum[wid] = s;
    __syncthreads();
    s = ssum[0] + ssum[1] + ssum[2] + ssum[3];   // warps 0-3 cover all j once
    float alpha = a0 - m - log2f(s) * LN2_F;
    __syncthreads();

    for (int t = 0; t < TT - 1; t++) {
        const int p = t & 1;
        if (t + 2 < TT - 1) prefetch(t + 2);
        asm volatile("cp.async.commit_group;" ::: "memory");

        float mm = warpMax(alpha);
        if (lane == 0) smax[p][wid] = mm;
        __syncthreads();
        mm = smax[p][0];
#pragma unroll
        for (int w = 1; w < 8; w++) mm = fmaxf(mm, smax[p][w]);
        if (tid < 128) w_s[p][j] = exp2f((alpha - mm) * LOG2E_F);
        asm volatile("cp.async.wait_group %0;" :: "n"(2) : "memory");
        __syncthreads();

        const size_t off = (size_t)(t % 3) * PBUF8;
        float acc0 = 0.f, acc1 = 0.f, acc2 = 0.f, acc3 = 0.f;
#pragma unroll
        for (int ii = 0; ii < 16; ii++) {
            const int i = ic * 16 + ii;
            uint32_t u = *reinterpret_cast<const uint32_t*>(ps + off + i * 128 + jg * 4);
            float wi = w_s[p][i];
            __half2_raw r01 = __nv_cvt_fp8x2_to_halfraw2(
                (__nv_fp8x2_storage_t)(u & 0xffffu), __NV_E4M3);
            __half2_raw r23 = __nv_cvt_fp8x2_to_halfraw2(
                (__nv_fp8x2_storage_t)(u >> 16), __NV_E4M3);
            float2 f01 = __half22float2(*reinterpret_cast<__half2*>(&r01));
            float2 f23 = __half22float2(*reinterpret_cast<__half2*>(&r23));
            acc0 = fmaf(wi, f01.x, acc0);
            acc1 = fmaf(wi, f01.y, acc1);
            acc2 = fmaf(wi, f23.x, acc2);
            acc3 = fmaf(wi, f23.y, acc3);
        }
        red[p][ic][jg * 4 + 0] = acc0;
        red[p][ic][jg * 4 + 1] = acc1;
        red[p][ic][jg * 4 + 2] = acc2;
        red[p][ic][jg * 4 + 3] = acc3;
        __syncthreads();
        float tot = red[p][0][j];
#pragma unroll
        for (int w = 1; w < 8; w++) tot += red[p][w][j];
        float ea = *reinterpret_cast<const float*>(ps + 3 * PBUF8 + (t % 3) * EABUF + j * 4);
        alpha = mm + log2f(tot) * LN2_F + (ea - rl);
    }

    float mm = warpMax(alpha);
    if (lane == 0) smax[0][wid] = mm;
    __syncthreads();
    mm = smax[0][0];
#pragma unroll
    for (int w = 1; w < 8; w++) mm = fmaxf(mm, smax[0][w]);
    float ee = exp2f((alpha - mm) * LOG2E_F);
    float ss = warpSum(ee);
    if (lane == 0) ssum[wid] = ss;
    __syncthreads();
    if (tid == 0) {
        float stot = ssum[0] + ssum[1] + ssum[2] + ssum[3];
        d_Chain[n] = mm + log2f(stot) * LN2_F;
    }
}

__global__ void k_final(float* out, int out_size)
{
    __shared__ float sh;
    if (threadIdx.x == 0) {
        float s = 0.0f;
        for (int i = 0; i < NB; i++) s += d_Chain[i];
        sh = -s / (float)NB;
    }
    __syncthreads();
    for (int i = threadIdx.x; i < out_size; i += blockDim.x) out[i] = sh;
}

extern "C" void kernel_launch(void* const* d_in, const int* in_sizes, int n_in,
                              void* d_out, int out_size)
{
    (void)in_sizes; (void)n_in;
    const int*   x             = (const int*)d_in[0];
    const float* embed_w       = (const float*)d_in[1];
    const float* trans_w       = (const float*)d_in[2];
    const float* start_w       = (const float*)d_in[3];
    const float* start_b       = (const float*)d_in[4];
    const float* emb_cluster_w = (const float*)d_in[5];
    const float* emit_w        = (const float*)d_in[6];

    cudaFuncSetAttribute(k_mma, cudaFuncAttributeMaxDynamicSharedMemorySize, SMEM_MMA);
    cudaFuncSetAttribute(k_scan, cudaFuncAttributeMaxDynamicSharedMemorySize, SCAN_SMEM);

    // host-side resources (created once; no device memory involved)
    static cudaStream_t s1 = [] { cudaStream_t s; cudaStreamCreateWithFlags(&s, cudaStreamNonBlocking); return s; }();
    static cudaStream_t s2 = [] { cudaStream_t s; cudaStreamCreateWithFlags(&s, cudaStreamNonBlocking); return s; }();
    static cudaEvent_t evF = [] { cudaEvent_t e; cudaEventCreateWithFlags(&e, cudaEventDisableTiming); return e; }();
    static cudaEvent_t evE = [] { cudaEvent_t e; cudaEventCreateWithFlags(&e, cudaEventDisableTiming); return e; }();
    static cudaEvent_t evB = [] { cudaEvent_t e; cudaEventCreateWithFlags(&e, cudaEventDisableTiming); return e; }();

    // fork side streams off the capture (legacy) stream
    cudaEventRecord(evF, 0);
    cudaStreamWaitEvent(s1, evF, 0);
    cudaStreamWaitEvent(s2, evF, 0);

    // s1: emission chain (only needed by k_scan)
    k_emit_gemm<<<VTILES, 256, 0, s1>>>(emit_w, emb_cluster_w);
    k_lse_final<<<KC, 256, 0, s1>>>();
    cudaEventRecord(evE, s1);

    // s2: trans_w conversion (only needed by k_mma)
    k_prepB<<<4096, 256, 0, s2>>>(trans_w);
    cudaEventRecord(evB, s2);

    // main: dedup -> prepA -> (join prepB) -> mma -> (join emit) -> scan
    k_zero<<<(VV + 255) / 256, 256>>>();
    k_mark<<<(RR + 255) / 256, 256>>>(x);
    k_rowslot<<<(RR + 255) / 256, 256>>>(x);
    k_prepA<<<RPAD, 64>>>(embed_w);
    cudaStreamWaitEvent(0, evB, 0);
    k_mma<<<dim3(128 / MT_GROUP, 128), 256, SMEM_MMA>>>(0);
    cudaStreamWaitEvent(0, evE, 0);
    k_scan<<<NB, 256, SCAN_SMEM>>>(x, start_w, start_b);
    k_final<<<1, 64>>>((float*)d_out, out_size);
}

// round 17
// speedup vs baseline: 1.0748x; 1.0004x over previous
#include <cuda_runtime.h>
#include <cuda_fp16.h>
#include <cuda_fp8.h>
#include <cstdint>

#define LOG2E_F 1.4426950408889634f
#define LN2_F   0.6931471805599453f

constexpr int NB = 64;       // batch N
constexpr int TT = 256;      // T
constexpr int VV = 32000;    // vocab
constexpr int EE = 256;      // embed dim
constexpr int KC = 128;      // clusters K
constexpr int RR = (TT - 1) * NB;   // 16320 (t,n) rows
constexpr int RPAD = 16384;         // padded unique-slot capacity
constexpr int VTILES = VV / 64;     // 500

// ------- static scratch (__device__ globals; no allocation allowed) -------
__device__ __align__(16) __nv_fp8_storage_t d_P8[(size_t)RPAD * KC * KC]; // [slot][i][j] fp8 probs
__device__ __align__(16) float  d_LogitsT[(size_t)VV * KC];  // [v][c]
__device__ __align__(16) __half d_Ah[(size_t)RPAD * EE]; // unique-token embeds f16
__device__ __align__(16) __half d_Bh[(size_t)KC * KC * EE]; // trans_w f16
__device__ float  d_PM[VTILES * KC];
__device__ float  d_PS[VTILES * KC];
__device__ float  d_RowLse[KC];
__device__ float  d_Chain[NB];
__device__ int    d_Mark[VV];
__device__ int    d_Slot[VV];
__device__ int    d_Inv[RPAD];
__device__ int    d_RowSlot[RR];
__device__ int    d_Uc;

__device__ __forceinline__ uint32_t smem_u32(const void* p) {
    uint32_t a;
    asm("{ .reg .u64 t; cvta.to.shared.u64 t, %1; cvt.u32.u64 %0, t; }" : "=r"(a) : "l"(p));
    return a;
}
__device__ __forceinline__ void cpa16(uint32_t saddr, const void* g) {
    asm volatile("cp.async.cg.shared.global [%0], [%1], 16;" :: "r"(saddr), "l"(g));
}
__device__ __forceinline__ void cpa4(uint32_t saddr, const void* g) {
    asm volatile("cp.async.ca.shared.global [%0], [%1], 4;" :: "r"(saddr), "l"(g));
}
__device__ __forceinline__ void ldsm_x4(uint32_t& r0, uint32_t& r1, uint32_t& r2, uint32_t& r3,
                                        uint32_t addr) {
    asm volatile("ldmatrix.sync.aligned.m8n8.x4.shared.b16 {%0,%1,%2,%3}, [%4];"
                 : "=r"(r0), "=r"(r1), "=r"(r2), "=r"(r3) : "r"(addr));
}
// f16 inputs, f16 accumulators (2 regs C/D)
__device__ __forceinline__ void mma_f16acc(uint32_t& d0, uint32_t& d1,
                                           uint32_t a0, uint32_t a1, uint32_t a2, uint32_t a3,
                                           uint32_t b0, uint32_t b1) {
    asm volatile("mma.sync.aligned.m16n8k16.row.col.f16.f16.f16.f16 "
                 "{%0,%1}, {%2,%3,%4,%5}, {%6,%7}, {%0,%1};"
                 : "+r"(d0), "+r"(d1)
                 : "r"(a0), "r"(a1), "r"(a2), "r"(a3), "r"(b0), "r"(b1));
}

__device__ __forceinline__ float warpMax(float v) {
#pragma unroll
    for (int o = 16; o; o >>= 1) v = fmaxf(v, __shfl_xor_sync(0xffffffffu, v, o));
    return v;
}
__device__ __forceinline__ float warpSum(float v) {
#pragma unroll
    for (int o = 16; o; o >>= 1) v += __shfl_xor_sync(0xffffffffu, v, o);
    return v;
}

// =====================================================================
// Token dedup (atomic slot assignment; slot order run-varying but output
// is bitwise-invariant to the slot permutation)
// =====================================================================
__global__ void __launch_bounds__(256) k_zero()
{
    int i = blockIdx.x * 256 + threadIdx.x;
    if (i < VV) d_Mark[i] = 0;
    if (i == 0) d_Uc = 0;
}

__global__ void __launch_bounds__(256) k_mark(const int* __restrict__ x)
{
    int r = blockIdx.x * 256 + threadIdx.x;
    if (r < RR) {
        int t = r >> 6, n = r & 63;
        int v = x[n * TT + t];
        if (atomicCAS(&d_Mark[v], 0, 1) == 0) {
            int s = atomicAdd(&d_Uc, 1);
            d_Slot[v] = s;
            d_Inv[s] = v;
        }
    }
}

__global__ void __launch_bounds__(256) k_rowslot(const int* __restrict__ x)
{
    int r = blockIdx.x * 256 + threadIdx.x;
    if (r < RR) {
        int t = r >> 6, n = r & 63;
        d_RowSlot[r] = d_Slot[x[n * TT + t]];
    }
}

// =====================================================================
// Operand prep -> f16 (unique tokens only)
// =====================================================================
__global__ void __launch_bounds__(64) k_prepA(const float* __restrict__ embed_w)
{
    const int u = blockIdx.x;
    if (u >= d_Uc) return;
    const int tid = threadIdx.x;
    int tok = d_Inv[u];
    float4 f = *reinterpret_cast<const float4*>(embed_w + (size_t)tok * EE + tid * 4);
    union { __half2 h[2]; uint2 q; } pk;
    pk.h[0] = __floats2half2_rn(f.x, f.y);
    pk.h[1] = __floats2half2_rn(f.z, f.w);
    *reinterpret_cast<uint2*>(d_Ah + (size_t)u * EE + tid * 4) = pk.q;
}

__global__ void __launch_bounds__(256) k_prepB(const float* __restrict__ trans_w)
{
    size_t idx = (size_t)blockIdx.x * blockDim.x + threadIdx.x;
    float4 f = *reinterpret_cast<const float4*>(trans_w + idx * 4);
    union { __half2 h[2]; uint2 q; } pk;
    pk.h[0] = __floats2half2_rn(f.x, f.y);
    pk.h[1] = __floats2half2_rn(f.z, f.w);
    *reinterpret_cast<uint2*>(d_Bh + idx * 4) = pk.q;
}

// =====================================================================
// Phase A v4: B-stationary, ktile=64, 2-stage double buffer (R15 winner).
// =====================================================================
constexpr int NKT      = 4;             // 256 / 64
constexpr int MT_GROUP = 8;
constexpr int AROWB    = 144;           // 128B data + 16 pad (ldsm conflict-free)
constexpr int ASTAGE   = 128 * AROWB;   // 18432
constexpr int BROWB    = 528;           // 512B data + 16 pad
constexpr int BBYTES   = 128 * BROWB;   // 67584
constexpr int SMEM_MMA = BBYTES + 2 * ASTAGE;  // 104448
constexpr int ESTRIDE  = 66;            // epilogue u32 row stride (fits in ASTAGE)

__device__ __forceinline__ void load_Astage(uint32_t Asm, int kk, int Mt0, int tid)
{
    const int Mt = Mt0 + (kk >> 2);
    const int kt = kk & 3;
    const uint32_t abase = Asm + (kk & 1) * ASTAGE;
#pragma unroll
    for (int it = 0; it < 4; it++) {
        int chunk = tid + it * 256;        // 0..1023
        int row   = chunk >> 3;
        int c     = chunk & 7;
        const __half* g = d_Ah + ((size_t)(Mt * 128 + row)) * EE + kt * 64 + c * 8;
        cpa16(abase + row * AROWB + c * 16, g);
    }
}

__global__ void __launch_bounds__(256, 2) k_mma(int dummy)
{
    const int U = d_Uc;
    extern __shared__ char smem[];
    const uint32_t Bsm = smem_u32(smem);
    const uint32_t Asm = Bsm + BBYTES;
    const int iC  = blockIdx.y;
    const int tid = threadIdx.x;
    const int wid = tid >> 5;
    const int lane = tid & 31;
    const int wm = (wid & 1) * 64;
    const int wn = (wid >> 1) * 32;
    const int lr = lane & 15;
    const int lu = lane >> 4;

    const int Mt0 = blockIdx.x * MT_GROUP;
    int remain = (U - Mt0 * 128 + 127) >> 7;
    if (remain <= 0) return;
    const int gcnt = remain < MT_GROUP ? remain : MT_GROUP;
    const int KTOT = gcnt * NKT;

    // ---- load full B tile (iC) once ----
    {
        const __half* gB = d_Bh + (size_t)iC * 128 * EE;
#pragma unroll
        for (int it = 0; it < 16; it++) {
            int chunk = tid + it * 256;    // 0..4095
            int row   = chunk >> 5;
            int c     = chunk & 31;
            cpa16(Bsm + row * BROWB + c * 16, gB + (size_t)row * EE + c * 8);
        }
        asm volatile("cp.async.commit_group;" ::: "memory");
    }

    // A prologue: stage 0
    load_Astage(Asm, 0, Mt0, tid);
    asm volatile("cp.async.commit_group;" ::: "memory");

    uint32_t acc[4][4][2];
#pragma unroll
    for (int a = 0; a < 4; a++)
#pragma unroll
        for (int b = 0; b < 4; b++) { acc[a][b][0] = 0u; acc[a][b][1] = 0u; }

    const int er = lane >> 2;
    const int uc = lane & 3;

    for (int kk = 0; kk < KTOT; kk++) {
        const int kt = kk & 3;
        asm volatile("cp.async.wait_group %0;" :: "n"(0) : "memory");
        __syncthreads();
        if (kk + 1 < KTOT) load_Astage(Asm, kk + 1, Mt0, tid);
        asm volatile("cp.async.commit_group;" ::: "memory");

        const uint32_t Abase = Asm + (kk & 1) * ASTAGE;
#pragma unroll
        for (int s = 0; s < 4; s++) {
            uint32_t af[4][4];
#pragma unroll
            for (int mi = 0; mi < 4; mi++)
                ldsm_x4(af[mi][0], af[mi][1], af[mi][2], af[mi][3],
                        Abase + (wm + mi * 16 + lr) * AROWB + s * 32 + lu * 16);
            uint32_t bf[2][4];
#pragma unroll
            for (int p = 0; p < 2; p++)
                ldsm_x4(bf[p][0], bf[p][1], bf[p][2], bf[p][3],
                        Bsm + (wn + p * 16 + lr) * BROWB + kt * 128 + s * 32 + lu * 16);
#pragma unroll
            for (int mi = 0; mi < 4; mi++)
#pragma unroll
                for (int ni = 0; ni < 4; ni++) {
                    int p = ni >> 1, hi = ni & 1;
                    mma_f16acc(acc[mi][ni][0], acc[mi][ni][1],
                               af[mi][0], af[mi][1], af[mi][2], af[mi][3],
                               bf[p][hi], bf[p][2 + hi]);
                }
        }

        if (kt == 3) {
            const int Mt = Mt0 + (kk >> 2);
            uint32_t* ep = reinterpret_cast<uint32_t*>(smem + BBYTES + (kk & 1) * ASTAGE);
            __syncthreads();
#pragma unroll
            for (int h = 0; h < 2; h++) {
                if ((wid & 1) == h) {
#pragma unroll
                    for (int mi = 0; mi < 4; mi++)
#pragma unroll
                        for (int ni = 0; ni < 4; ni++) {
                            int lrow = mi * 16 + er;
                            int ucol = (wn >> 1) + ni * 4 + uc;
                            ep[(size_t)lrow * ESTRIDE + ucol] = acc[mi][ni][0];
                            ep[(size_t)(lrow + 8) * ESTRIDE + ucol] = acc[mi][ni][1];
                        }
                }
                __syncthreads();
                {
                    const int lrow = tid >> 2;
                    const int qtr  = tid & 3;
                    const int r    = Mt * 128 + h * 64 + lrow;
                    float v[32];
                    const uint32_t* rp = ep + (size_t)lrow * ESTRIDE + qtr * 16;
#pragma unroll
                    for (int q = 0; q < 8; q++) {
                        uint2 u2 = *reinterpret_cast<const uint2*>(rp + q * 2);
                        float2 f0 = __half22float2(*reinterpret_cast<__half2*>(&u2.x));
                        float2 f1 = __half22float2(*reinterpret_cast<__half2*>(&u2.y));
                        v[q * 4 + 0] = f0.x; v[q * 4 + 1] = f0.y;
                        v[q * 4 + 2] = f1.x; v[q * 4 + 3] = f1.y;
                    }
                    float m = -3.4e38f;
#pragma unroll
                    for (int q = 0; q < 32; q++) m = fmaxf(m, v[q]);
                    m = fmaxf(m, __shfl_xor_sync(0xffffffffu, m, 1));
                    m = fmaxf(m, __shfl_xor_sync(0xffffffffu, m, 2));
                    float s = 0.0f;
#pragma unroll
                    for (int q = 0; q < 32; q++) { v[q] = exp2f((v[q] - m) * LOG2E_F); s += v[q]; }
                    s += __shfl_xor_sync(0xffffffffu, s, 1);
                    s += __shfl_xor_sync(0xffffffffu, s, 2);
                    float inv = 1.0f / s;
                    if (r < U) {
                        union { __nv_fp8x2_storage_t hh[16]; uint4 q4[2]; } pk;
#pragma unroll
                        for (int q = 0; q < 16; q++)
                            pk.hh[q] = __nv_cvt_float2_to_fp8x2(
                                make_float2(v[2 * q] * inv, v[2 * q + 1] * inv),
                                __NV_SATFINITE, __NV_E4M3);
                        uint4* op = reinterpret_cast<uint4*>(
                            d_P8 + ((size_t)r * KC + iC) * KC + qtr * 32);
                        op[0] = pk.q4[0];
                        op[1] = pk.q4[1];
                    }
                }
                __syncthreads();
            }
#pragma unroll
            for (int a = 0; a < 4; a++)
#pragma unroll
                for (int b = 0; b < 4; b++) { acc[a][b][0] = 0u; acc[a][b][1] = 0u; }
        }
    }
    (void)dummy;
}

// =====================================================================
// Emission logits GEMM + partial lse + parallel final lse
// =====================================================================
__global__ void __launch_bounds__(256) k_emit_gemm(const float* __restrict__ emit_w,
                                                   const float* __restrict__ emb_cluster_w)
{
    const int vt = blockIdx.x;
    __shared__ float avs[16][65];
    __shared__ float bvs[16][129];
    __shared__ float pmS[8][128];
    __shared__ float psS[8][128];

    const int tid   = threadIdx.x;
    const int lane  = tid & 31;
    const int wg    = tid >> 5;
    const int rbase = wg * 8;
    const int cbase = lane * 4;

    float acc[8][4];
#pragma unroll
    for (int a = 0; a < 8; a++)
#pragma unroll
        for (int b = 0; b < 4; b++) acc[a][b] = 0.0f;

    for (int k0 = 0; k0 < KC; k0 += 16) {
#pragma unroll
        for (int it = 0; it < 4; it++) {
            int u = tid + it * 256;
            int kk = u & 15, row = u >> 4;
            avs[kk][row] = emit_w[(size_t)(vt * 64 + row) * KC + k0 + kk];
        }
#pragma unroll
        for (int it = 0; it < 8; it++) {
            int u = tid + it * 256;
            int kk = u & 15, c = u >> 4;
            bvs[kk][c] = emb_cluster_w[(size_t)c * KC + k0 + kk];
        }
        __syncthreads();
#pragma unroll
        for (int kk = 0; kk < 16; kk++) {
            float av[8], bv[4];
#pragma unroll
            for (int r2 = 0; r2 < 8; r2++) av[r2] = avs[kk][rbase + r2];
#pragma unroll
            for (int c2 = 0; c2 < 4; c2++) bv[c2] = bvs[kk][cbase + c2];
#pragma unroll
            for (int r2 = 0; r2 < 8; r2++)
#pragma unroll
                for (int c2 = 0; c2 < 4; c2++)
                    acc[r2][c2] = fmaf(av[r2], bv[c2], acc[r2][c2]);
        }
        __syncthreads();
    }

    float pm[4], ps[4];
#pragma unroll
    for (int c2 = 0; c2 < 4; c2++) { pm[c2] = -3.4e38f; ps[c2] = 0.0f; }
#pragma unroll
    for (int r2 = 0; r2 < 8; r2++) {
        int v = vt * 64 + rbase + r2;
        float4 f4 = make_float4(acc[r2][0], acc[r2][1], acc[r2][2], acc[r2][3]);
        *reinterpret_cast<float4*>(&d_LogitsT[(size_t)v * KC + cbase]) = f4;
#pragma unroll
        for (int c2 = 0; c2 < 4; c2++) pm[c2] = fmaxf(pm[c2], acc[r2][c2]);
    }
#pragma unroll
    for (int r2 = 0; r2 < 8; r2++)
#pragma unroll
        for (int c2 = 0; c2 < 4; c2++)
            ps[c2] += exp2f((acc[r2][c2] - pm[c2]) * LOG2E_F);

#pragma unroll
    for (int c2 = 0; c2 < 4; c2++) { pmS[wg][cbase + c2] = pm[c2]; psS[wg][cbase + c2] = ps[c2]; }
    __syncthreads();
    if (tid < 128) {
        float m = pmS[0][tid];
#pragma unroll
        for (int w = 1; w < 8; w++) m = fmaxf(m, pmS[w][tid]);
        float s = 0.0f;
#pragma unroll
        for (int w = 0; w < 8; w++) s += psS[w][tid] * exp2f((pmS[w][tid] - m) * LOG2E_F);
        d_PM[vt * KC + tid] = m;
        d_PS[vt * KC + tid] = s;
    }
}

__global__ void __launch_bounds__(256) k_lse_final()
{
    __shared__ float sred[256];
    const int c   = blockIdx.x;
    const int tid = threadIdx.x;

    float m = -3.4e38f;
    for (int b = tid; b < VTILES; b += 256) m = fmaxf(m, d_PM[b * KC + c]);
    sred[tid] = m;
    __syncthreads();
    for (int o = 128; o; o >>= 1) {
        if (tid < o) sred[tid] = fmaxf(sred[tid], sred[tid + o]);
        __syncthreads();
    }
    float gm = sred[0];
    __syncthreads();

    float s = 0.0f;
    for (int b = tid; b < VTILES; b += 256)
        s += d_PS[b * KC + c] * exp2f((d_PM[b * KC + c] - gm) * LOG2E_F);
    sred[tid] = s;
    __syncthreads();
    for (int o = 128; o; o >>= 1) {
        if (tid < o) sred[tid] += sred[tid + o];
        __syncthreads();
    }
    if (tid == 0) d_RowLse[c] = gm + log2f(sred[0]) * LN2_F;
}

// =====================================================================
// Phase B: lag-normalized scan — no per-step max reduction, 2 syncs/step.
// beta = alpha - off, with off accumulating lse(beta) one step behind;
// lse(beta) stays bounded (~ -|log p(w_t)|), so exp(beta) is fp32-safe.
// =====================================================================
constexpr int PBUF8     = KC * KC;               // 16384 bytes/stage
constexpr int EABUF     = KC * 4;                // 512
constexpr int SCAN_SMEM = 3 * (PBUF8 + EABUF);   // 50688

__global__ void __launch_bounds__(256) k_scan(const int* __restrict__ x,
                                              const float* __restrict__ start_w,
                                              const float* __restrict__ start_b)
{
    extern __shared__ __align__(16) char ps[];
    __shared__ float w_s[2][128];
    __shared__ float red[2][8][132];
    __shared__ float wpart[2][4];
    __shared__ float smax[8];
    __shared__ float ssum[8];

    const int n    = blockIdx.x;
    const int tid  = threadIdx.x;
    const int lane = tid & 31;
    const int wid  = tid >> 5;       // 0..7
    const int j    = tid & 127;      // duplicated across halves
    const int jg   = lane;
    const int ic   = wid;            // i-chunk of 16
    const uint32_t sbase  = smem_u32(ps);
    const uint32_t eabase = sbase + 3 * PBUF8;
    const float rl = d_RowLse[j];

    auto prefetch = [&](int t) {
        const int r = t * NB + n;
        const int slot = d_RowSlot[r];
        const char* gp = reinterpret_cast<const char*>(d_P8 + (size_t)slot * KC * KC);
        uint32_t dst = sbase + (t % 3) * PBUF8;
#pragma unroll
        for (int k = 0; k < 4; k++) {
            int idx = tid + k * 256;
            cpa16(dst + idx * 16, gp + idx * 16);
        }
        if (tid < 128) {
            const int w = x[n * TT + t + 1];
            cpa4(eabase + (t % 3) * EABUF + tid * 4, d_LogitsT + (size_t)w * KC + tid);
        }
    };

    prefetch(0);
    asm volatile("cp.async.commit_group;" ::: "memory");
    prefetch(1);
    asm volatile("cp.async.commit_group;" ::: "memory");

    // exact init: beta = log_softmax(start); lse(beta) = 0
    float a0 = start_w[j] + start_b[j];
    float m = warpMax(a0);
    if (lane == 0) smax[wid] = m;
    __syncthreads();
    m = smax[0];
#pragma unroll
    for (int w = 1; w < 8; w++) m = fmaxf(m, smax[w]);
    float e = exp2f((a0 - m) * LOG2E_F);
    float s = warpSum(e);
    if (lane == 0) ssum[wid] = s;
    __syncthreads();
    s = ssum[0] + ssum[1] + ssum[2] + ssum[3];
    float beta = a0 - m - log2f(s) * LN2_F;
    float off  = 0.0f;
    __syncthreads();

    for (int t = 0; t < TT - 1; t++) {
        const int p = t & 1;
        if (t + 2 < TT - 1) prefetch(t + 2);
        asm volatile("cp.async.commit_group;" ::: "memory");

        // w = exp(beta) directly — no max shift needed (lse(beta) bounded)
        float w = exp2f(beta * LOG2E_F);
        if (tid < 128) w_s[p][j] = w;
        float wp = warpSum(w);                    // warps 0-3 cover all j once
        if (lane == 0 && wid < 4) wpart[p][wid] = wp;
        asm volatile("cp.async.wait_group %0;" :: "n"(2) : "memory");
        __syncthreads();                          // publishes w_s + wpart

        const size_t boff = (size_t)(t % 3) * PBUF8;
        float acc0 = 0.f, acc1 = 0.f, acc2 = 0.f, acc3 = 0.f;
#pragma unroll
        for (int ii = 0; ii < 16; ii++) {
            const int i = ic * 16 + ii;
            uint32_t u = *reinterpret_cast<const uint32_t*>(ps + boff + i * 128 + jg * 4);
            float wi = w_s[p][i];
            __half2_raw r01 = __nv_cvt_fp8x2_to_halfraw2(
                (__nv_fp8x2_storage_t)(u & 0xffffu), __NV_E4M3);
            __half2_raw r23 = __nv_cvt_fp8x2_to_halfraw2(
                (__nv_fp8x2_storage_t)(u >> 16), __NV_E4M3);
            float2 f01 = __half22float2(*reinterpret_cast<__half2*>(&r01));
            float2 f23 = __half22float2(*reinterpret_cast<__half2*>(&r23));
            acc0 = fmaf(wi, f01.x, acc0);
            acc1 = fmaf(wi, f01.y, acc1);
            acc2 = fmaf(wi, f23.x, acc2);
            acc3 = fmaf(wi, f23.y, acc3);
        }
        red[p][ic][jg * 4 + 0] = acc0;
        red[p][ic][jg * 4 + 1] = acc1;
        red[p][ic][jg * 4 + 2] = acc2;
        red[p][ic][jg * 4 + 3] = acc3;
        __syncthreads();                          // publishes red
        float tot = red[p][0][j];
#pragma unroll
        for (int w2 = 1; w2 < 8; w2++) tot += red[p][w2][j];
        float S = log2f(wpart[p][0] + wpart[p][1] + wpart[p][2] + wpart[p][3]) * LN2_F;
        float ea = *reinterpret_cast<const float*>(ps + 3 * PBUF8 + (t % 3) * EABUF + j * 4);
        beta = log2f(tot) * LN2_F + (ea - rl) - S;
        off += S;
        // no trailing sync: next step writes opposite-parity buffers
    }

    // final: chain = lse_j(beta) + off
    float mm = warpMax(beta);
    if (lane == 0) smax[wid] = mm;
    __syncthreads();
    mm = smax[0];
#pragma unroll
    for (int w = 1; w < 8; w++) mm = fmaxf(mm, smax[w]);
    float ee = exp2f((beta - mm) * LOG2E_F);
    float ss = warpSum(ee);
    if (lane == 0) ssum[wid] = ss;
    __syncthreads();
    if (tid == 0) {
        float stot = ssum[0] + ssum[1] + ssum[2] + ssum[3];
        d_Chain[n] = mm + log2f(stot) * LN2_F + off;
    }
}

__global__ void k_final(float* out, int out_size)
{
    __shared__ float sh;
    if (threadIdx.x == 0) {
        float s = 0.0f;
        for (int i = 0; i < NB; i++) s += d_Chain[i];
        sh = -s / (float)NB;
    }
    __syncthreads();
    for (int i = threadIdx.x; i < out_size; i += blockDim.x) out[i] = sh;
}

extern "C" void kernel_launch(void* const* d_in, const int* in_sizes, int n_in,
                              void* d_out, int out_size)
{
    (void)in_sizes; (void)n_in;
    const int*   x             = (const int*)d_in[0];
    const float* embed_w       = (const float*)d_in[1];
    const float* trans_w       = (const float*)d_in[2];
    const float* start_w       = (const float*)d_in[3];
    const float* start_b       = (const float*)d_in[4];
    const float* emb_cluster_w = (const float*)d_in[5];
    const float* emit_w        = (const float*)d_in[6];

    cudaFuncSetAttribute(k_mma, cudaFuncAttributeMaxDynamicSharedMemorySize, SMEM_MMA);
    cudaFuncSetAttribute(k_scan, cudaFuncAttributeMaxDynamicSharedMemorySize, SCAN_SMEM);

    // host-side resources (created once; no device memory involved)
    static cudaStream_t s1 = [] { cudaStream_t s; cudaStreamCreateWithFlags(&s, cudaStreamNonBlocking); return s; }();
    static cudaStream_t s2 = [] { cudaStream_t s; cudaStreamCreateWithFlags(&s, cudaStreamNonBlocking); return s; }();
    static cudaEvent_t evF = [] { cudaEvent_t e; cudaEventCreateWithFlags(&e, cudaEventDisableTiming); return e; }();
    static cudaEvent_t evE = [] { cudaEvent_t e; cudaEventCreateWithFlags(&e, cudaEventDisableTiming); return e; }();
    static cudaEvent_t evB = [] { cudaEvent_t e; cudaEventCreateWithFlags(&e, cudaEventDisableTiming); return e; }();

    // fork side streams off the capture (legacy) stream
    cudaEventRecord(evF, 0);
    cudaStreamWaitEvent(s1, evF, 0);
    cudaStreamWaitEvent(s2, evF, 0);

    // s1: emission chain (only needed by k_scan)
    k_emit_gemm<<<VTILES, 256, 0, s1>>>(emit_w, emb_cluster_w);
    k_lse_final<<<KC, 256, 0, s1>>>();
    cudaEventRecord(evE, s1);

    // s2: trans_w conversion (only needed by k_mma)
    k_prepB<<<4096, 256, 0, s2>>>(trans_w);
    cudaEventRecord(evB, s2);

    // main: dedup -> prepA -> (join prepB) -> mma -> (join emit) -> scan
    k_zero<<<(VV + 255) / 256, 256>>>();
    k_mark<<<(RR + 255) / 256, 256>>>(x);
    k_rowslot<<<(RR + 255) / 256, 256>>>(x);
    k_prepA<<<RPAD, 64>>>(embed_w);
    cudaStreamWaitEvent(0, evB, 0);
    k_mma<<<dim3(128 / MT_GROUP, 128), 256, SMEM_MMA>>>(0);
    cudaStreamWaitEvent(0, evE, 0);
    k_scan<<<NB, 256, SCAN_SMEM>>>(x, start_w, start_b);
    k_final<<<1, 64>>>((float*)d_out, out_size);
}